// round 8
// baseline (speedup 1.0000x reference)
#include <cuda_runtime.h>

// out[b,j,h] = (1/N) * sum_i sum_g W[b,i,j,h,g] * x[b,i,g]
// B=16, N=32, H=64. W: 256 MiB fp32 streamed once.
//
// R8 (final): we are at the B300 path-independent LTS fabric cap (~6.5 TB/s
// measured across 6 structurally different kernels; doc'd "LDG.cv ≡ TMA,
// pattern-independent"). Kernel runs at 98% of 268MB/6.5TB/s. Last mechanism:
// issue the first W loads BEFORE the x-staging barrier so each CTA's first
// DRAM latency overlaps the prologue instead of following it, and keep a
// depth-1 register prefetch through the loop. Stagger removed (proven
// neutral, cost extra ALU). __stwt on outputs (no L2 pollution).

#define BB 16
#define NN 32
#define HH 64

__global__ __launch_bounds__(256, 4)
void msg_nn_kernel(const float4* __restrict__ W,
                   const float4* __restrict__ X,
                   float* __restrict__ out)
{
    const int bj = blockIdx.x;      // 0..511
    const int b  = bj >> 5;
    const int j  = bj & (NN - 1);
    const int t  = threadIdx.x;     // 0..255

    __shared__ float4 xs[NN * HH / 4];   // x[b,:,:] = 512 float4 = 8 KB

    const size_t tileF4 = (size_t)HH * HH / 4;        // 1024
    const size_t IS     = (size_t)NN * tileF4;        // 32768 f4 (i stride)
    const float4* Wp = W + ((size_t)b * NN * NN + j) * tileF4 + t;

    // Issue first W tile loads BEFORE the barrier: overlaps the first DRAM
    // round-trip with x staging + __syncthreads.
    float4 c0 = Wp[0];
    float4 c1 = Wp[256];
    float4 c2 = Wp[512];
    float4 c3 = Wp[768];

    // Stage x[b,:,:] into smem (512 float4, 2 per thread)
    const float4* xb = X + (size_t)b * (NN * HH / 4);
    xs[t]       = xb[t];
    xs[t + 256] = xb[t + 256];
    __syncthreads();

    const int g4 = t & 15;
    const int h0 = t >> 4;

    float acc0 = 0.f, acc1 = 0.f, acc2 = 0.f, acc3 = 0.f;

    #pragma unroll 2
    for (int i = 0; i < NN; ++i) {
        // Prefetch next i while computing current (depth-1 pipeline).
        float4 n0, n1, n2, n3;
        if (i + 1 < NN) {
            const float4* np = Wp + (size_t)(i + 1) * IS;
            n0 = np[0]; n1 = np[256]; n2 = np[512]; n3 = np[768];
        } else {
            n0 = n1 = n2 = n3 = make_float4(0.f, 0.f, 0.f, 0.f);
        }

        const float4 xv = xs[i * 16 + g4];
        acc0 += c0.x * xv.x + c0.y * xv.y + c0.z * xv.z + c0.w * xv.w;
        acc1 += c1.x * xv.x + c1.y * xv.y + c1.z * xv.z + c1.w * xv.w;
        acc2 += c2.x * xv.x + c2.y * xv.y + c2.z * xv.z + c2.w * xv.w;
        acc3 += c3.x * xv.x + c3.y * xv.y + c3.z * xv.z + c3.w * xv.w;

        c0 = n0; c1 = n1; c2 = n2; c3 = n3;
    }

    // Reduce 16 g-quads per h within each contiguous 16-lane group.
    const unsigned mask = 0xFFFFFFFFu;
    #pragma unroll
    for (int off = 8; off > 0; off >>= 1) {
        acc0 += __shfl_down_sync(mask, acc0, off);
        acc1 += __shfl_down_sync(mask, acc1, off);
        acc2 += __shfl_down_sync(mask, acc2, off);
        acc3 += __shfl_down_sync(mask, acc3, off);
    }

    if (g4 == 0) {
        const float sc = 1.0f / (float)NN;
        float* o = out + (size_t)bj * HH + h0;
        __stwt(o +  0, acc0 * sc);
        __stwt(o + 16, acc1 * sc);
        __stwt(o + 32, acc2 * sc);
        __stwt(o + 48, acc3 * sc);
    }
}

extern "C" void kernel_launch(void* const* d_in, const int* in_sizes, int n_in,
                              void* d_out, int out_size)
{
    const float4* W = (const float4*)d_in[0];   // edge_wgt [B,N,N,H,H] fp32
    const float4* X = (const float4*)d_in[1];   // node_hidden [B,N,H] fp32
    float* out = (float*)d_out;                 // [B,N,H] fp32

    msg_nn_kernel<<<BB * NN, 256>>>(W, X, out);   // 512 CTAs
}